// round 5
// baseline (speedup 1.0000x reference)
#include <cuda_runtime.h>

#define NMAX   160000
#define KCOUT  32
#define KCIN   32
#define KTAPS  27
#define WELEMS (KTAPS * KCIN * KCOUT)   // 27648
#define BLOCKS1 1480                    // conv grid: 8 warps/block

// ---- device scratch (no allocations allowed) ----
__device__ float g_conv[(size_t)NMAX * KCOUT];   // pre-BN conv output (20.5 MB)
__device__ float g_wt[WELEMS];                   // transposed weights [k][c/4][d][c%4]
__device__ float g_psum[BLOCKS1 * KCOUT];        // per-block channel sums
__device__ float g_psq [BLOCKS1 * KCOUT];        // per-block channel sum-of-squares
__device__ float g_scale[KCOUT];                 // rstd * gamma
__device__ float g_shift[KCOUT];                 // beta - mean * scale

// ---------------------------------------------------------------------------
// K0: transpose weight [k][c][d] -> [k][c>>2][d][c&3] so that lane d can load
//     a float4 covering 4 consecutive c for its output channel (coalesced).
// ---------------------------------------------------------------------------
__global__ void transpose_w_kernel(const float* __restrict__ w) {
    int i = blockIdx.x * blockDim.x + threadIdx.x;
    if (i < WELEMS) {
        int d = i & 31;
        int c = (i >> 5) & 31;
        int k = i >> 10;
        g_wt[k * 1024 + (c >> 2) * 128 + d * 4 + (c & 3)] = w[i];
    }
}

// ---------------------------------------------------------------------------
// K1: warp-per-row sparse conv + bias; accumulates per-block BN partials.
// ---------------------------------------------------------------------------
__global__ __launch_bounds__(256) void conv_kernel(
    const float* __restrict__ feat,   // [N,32]
    const int*   __restrict__ nbr,    // [N,27]
    const float* __restrict__ bias,   // [32]
    int n)
{
    const int lane  = threadIdx.x & 31;
    const int wloc  = threadIdx.x >> 5;                 // warp in block (0..7)
    const int warp  = blockIdx.x * 8 + wloc;
    const int nwarp = gridDim.x * 8;

    const float bv = __ldg(bias + lane);
    float bsum = 0.f, bsq = 0.f;

    for (int row = warp; row < n; row += nwarp) {
        int idx = -1;
        if (lane < KTAPS) idx = __ldg(nbr + (long)row * KTAPS + lane);
        unsigned m = __ballot_sync(0xffffffffu, idx >= 0);

        float acc = 0.f;
        while (m) {
            int k = __ffs(m) - 1;
            m &= (m - 1);
            int j = __shfl_sync(0xffffffffu, idx, k);

            const float4* fp = (const float4*)(feat + (long)j * 32);  // broadcast
            const float4* wp = (const float4*)(g_wt + k * 1024) + lane; // coalesced

            float4 f[8];
            #pragma unroll
            for (int t = 0; t < 8; ++t) f[t] = __ldg(fp + t);

            #pragma unroll
            for (int c4 = 0; c4 < 8; ++c4) {
                float4 w = __ldg(wp + c4 * 32);   // W[k][4*c4..4*c4+3][lane]
                acc += f[c4].x * w.x + f[c4].y * w.y
                     + f[c4].z * w.z + f[c4].w * w.w;
            }
        }

        float v = acc + bv;
        g_conv[(long)row * KCOUT + lane] = v;
        bsum += v;
        bsq  += v * v;
    }

    // block-level deterministic reduction of BN partials
    __shared__ float s_sum[8][32];
    __shared__ float s_sq [8][32];
    s_sum[wloc][lane] = bsum;
    s_sq [wloc][lane] = bsq;
    __syncthreads();
    if (threadIdx.x < 32) {
        float s = 0.f, q = 0.f;
        #pragma unroll
        for (int i = 0; i < 8; ++i) { s += s_sum[i][threadIdx.x]; q += s_sq[i][threadIdx.x]; }
        g_psum[blockIdx.x * 32 + threadIdx.x] = s;
        g_psq [blockIdx.x * 32 + threadIdx.x] = q;
    }
}

// ---------------------------------------------------------------------------
// K2: reduce block partials -> mean/var -> fused scale/shift. Single block.
// ---------------------------------------------------------------------------
__global__ void stats_kernel(const float* __restrict__ gamma,
                             const float* __restrict__ beta,
                             int n)
{
    __shared__ float ss[16][32];
    __shared__ float sq[16][32];
    const int ch = threadIdx.x & 31;
    const int sl = threadIdx.x >> 5;   // 512 threads -> 16 slices

    float s = 0.f, q = 0.f;
    for (int i = sl; i < BLOCKS1; i += 16) {
        s += g_psum[i * 32 + ch];
        q += g_psq [i * 32 + ch];
    }
    ss[sl][ch] = s;
    sq[sl][ch] = q;
    __syncthreads();

    if (threadIdx.x < 32) {
        float S = 0.f, Q = 0.f;
        #pragma unroll
        for (int i = 0; i < 16; ++i) { S += ss[i][threadIdx.x]; Q += sq[i][threadIdx.x]; }
        float inv_n = 1.f / (float)n;
        float mean  = S * inv_n;
        float var   = Q * inv_n - mean * mean;
        float rstd  = rsqrtf(var + 1e-5f);
        float sc    = rstd * __ldg(gamma + threadIdx.x);
        g_scale[threadIdx.x] = sc;
        g_shift[threadIdx.x] = __ldg(beta + threadIdx.x) - mean * sc;
    }
}

// ---------------------------------------------------------------------------
// K3: elementwise BN-apply + LeakyReLU, float4 vectorized (32 | 4).
// ---------------------------------------------------------------------------
__global__ __launch_bounds__(256) void finalize_kernel(float* __restrict__ out, int n4) {
    int i = blockIdx.x * blockDim.x + threadIdx.x;
    if (i >= n4) return;
    float4 v = ((const float4*)g_conv)[i];
    int cb = (i & 7) * 4;                       // channel base within row
    float4 sc = *(const float4*)(g_scale + cb);
    float4 sh = *(const float4*)(g_shift + cb);
    float4 o;
    o.x = v.x * sc.x + sh.x;
    o.y = v.y * sc.y + sh.y;
    o.z = v.z * sc.z + sh.z;
    o.w = v.w * sc.w + sh.w;
    o.x = (o.x >= 0.f) ? o.x : 0.01f * o.x;
    o.y = (o.y >= 0.f) ? o.y : 0.01f * o.y;
    o.z = (o.z >= 0.f) ? o.z : 0.01f * o.z;
    o.w = (o.w >= 0.f) ? o.w : 0.01f * o.w;
    ((float4*)out)[i] = o;
}

// ---------------------------------------------------------------------------
// kernel_launch — inputs per metadata order:
//   0: features [N,32] f32   1: neighbor_idx [N,27] i32   2: weight [27,32,32] f32
//   3: bias [32] f32         4: gamma [32] f32            5: beta [32] f32
// output: [N,32] f32
// ---------------------------------------------------------------------------
extern "C" void kernel_launch(void* const* d_in, const int* in_sizes, int n_in,
                              void* d_out, int out_size)
{
    const float* feat  = (const float*)d_in[0];
    const int*   nbr   = (const int*)  d_in[1];
    const float* w     = (const float*)d_in[2];
    const float* bias  = (const float*)d_in[3];
    const float* gamma = (const float*)d_in[4];
    const float* beta  = (const float*)d_in[5];
    float* out = (float*)d_out;

    int n = in_sizes[0] / KCIN;     // number of active voxels
    if (n > NMAX) n = NMAX;

    transpose_w_kernel<<<(WELEMS + 255) / 256, 256>>>(w);
    conv_kernel<<<BLOCKS1, 256>>>(feat, nbr, bias, n);
    stats_kernel<<<1, 512>>>(gamma, beta, n);
    int n4 = n * (KCOUT / 4);
    finalize_kernel<<<(n4 + 255) / 256, 256>>>(out, n4);
}